// round 11
// baseline (speedup 1.0000x reference)
#include <cuda_runtime.h>
#include <cuda_fp16.h>
#include <cstdint>

// Problem constants (LaplacianReg: B=32, V=65536, K=8, C=3)
#define BB 32
#define VV 65536
#define KK 8
#define CC 3
#define ROW (VV * CC)          // 196608 floats per batch row
#define VB (BB * CC)           // 96 elements per vertex in transposed scratch
#define RB (VB * 2)            // 192 bytes per vertex row
#define VPB 64                 // vertices per block in kernel 2
#define SROW 100               // smem staging row stride (floats)

// fp16 transposed scratch: d16[v][b*3+c] = out[b][v][c] - tgt[b][v][c].
// Row = 96 halves = 192B, 64B-aligned -> every row spans exactly 2 cache lines.
__device__ __align__(16) __half d16[(size_t)VV * VB];

// ---------------------------------------------------------------------------
// Kernel 1: fused difference + transpose (B,V,C) -> fp16 (V, B*C)
// ---------------------------------------------------------------------------
__global__ __launch_bounds__(256) void diff_transpose_kernel(
    const float* __restrict__ outp, const float* __restrict__ tgtp) {
    __shared__ float s[32 * 97];

    const int v0   = blockIdx.x * 32;
    const int warp = threadIdx.x >> 5;
    const int lane = threadIdx.x & 31;

    // Phase A: each warp loads 4 batch-rows (96 contiguous floats), coalesced.
    #pragma unroll
    for (int i = 0; i < 4; i++) {
        const int b = warp + 8 * i;
        const float* po = outp + (size_t)b * ROW + (size_t)v0 * CC;
        const float* pt = tgtp + (size_t)b * ROW + (size_t)v0 * CC;
        #pragma unroll
        for (int r = 0; r < 3; r++) {
            const int u = lane + 32 * r;
            s[b * 97 + u] = po[u] - pt[u];
        }
    }
    __syncthreads();

    // Phase B: 24 lanes per vertex row, each packs 4 halves -> one STG.64.
    #pragma unroll
    for (int i = 0; i < 4; i++) {
        const int vl = warp + 8 * i;
        if (lane < 24) {
            __half h[4];
            #pragma unroll
            for (int j = 0; j < 4; j++) {
                const int u = 4 * lane + j;       // 0..95
                const int b = u / 3;
                const int c = u - 3 * b;
                h[j] = __float2half_rn(s[b * 97 + vl * 3 + c]);
            }
            *reinterpret_cast<uint2*>(d16 + (size_t)(v0 + vl) * VB + 4 * lane) =
                *reinterpret_cast<const uint2*>(h);
        }
    }
}

// ---------------------------------------------------------------------------
// Kernel 2: full laplacian via 9-term gather (self weight 1.0) + square.
// Issue-count optimized: idx/w staged as int4/float4 (LDS.128), neighbor
// offsets pre-multiplied to byte offsets, 18 gathers in flight per warp
// (launch_bounds allows 64 regs so the loads actually stay live).
// ---------------------------------------------------------------------------
__global__ __launch_bounds__(256, 4) void lap_sq_kernel(
    const int*   __restrict__ idx,
    const float* __restrict__ wgt,
    float*       __restrict__ res) {
    __shared__ int4   si4[VPB * 2];   // 8 byte-offsets (j*192) per vertex
    __shared__ float4 sw4[VPB * 2];   // 8 weights per vertex
    __shared__ float  sn[VPB * SROW]; // (lap d)^2, vertex-major layout

    const int tid = threadIdx.x;
    const int v0  = blockIdx.x * VPB;

    // Stage idx (as byte offsets) + weights, coalesced (512 each).
    #pragma unroll
    for (int t = 0; t < (VPB * KK) / 256; t++) {
        const int i = t * 256 + tid;
        reinterpret_cast<int*>(si4)[i]   = idx[(size_t)v0 * KK + i] * RB;
        reinterpret_cast<float*>(sw4)[i] = wgt[(size_t)v0 * KK + i];
    }
    __syncthreads();

    const int warp    = tid >> 5;
    const int lane    = tid & 31;
    const bool active = lane < 24;
    const char* base  = reinterpret_cast<const char*>(d16) + lane * 8;

    #pragma unroll
    for (int vp = 0; vp < 4; vp++) {
        const int vlA = warp * 8 + 2 * vp;
        const int vlB = vlA + 1;

        // Packed idx/w reads: 8 LDS.128 per vertex pair (broadcast).
        const int4   oa0 = si4[vlA * 2], oa1 = si4[vlA * 2 + 1];
        const int4   ob0 = si4[vlB * 2], ob1 = si4[vlB * 2 + 1];
        const float4 wa0 = sw4[vlA * 2], wa1 = sw4[vlA * 2 + 1];
        const float4 wb0 = sw4[vlB * 2], wb1 = sw4[vlB * 2 + 1];

        if (active) {
            // Issue all 18 gathers (self + 8 neighbors, two vertices) first.
            uint2 sA, sB, gA[KK], gB[KK];
            sA    = *reinterpret_cast<const uint2*>(base + (v0 + vlA) * RB);
            gA[0] = *reinterpret_cast<const uint2*>(base + oa0.x);
            gA[1] = *reinterpret_cast<const uint2*>(base + oa0.y);
            gA[2] = *reinterpret_cast<const uint2*>(base + oa0.z);
            gA[3] = *reinterpret_cast<const uint2*>(base + oa0.w);
            gA[4] = *reinterpret_cast<const uint2*>(base + oa1.x);
            gA[5] = *reinterpret_cast<const uint2*>(base + oa1.y);
            gA[6] = *reinterpret_cast<const uint2*>(base + oa1.z);
            gA[7] = *reinterpret_cast<const uint2*>(base + oa1.w);
            sB    = *reinterpret_cast<const uint2*>(base + (v0 + vlB) * RB);
            gB[0] = *reinterpret_cast<const uint2*>(base + ob0.x);
            gB[1] = *reinterpret_cast<const uint2*>(base + ob0.y);
            gB[2] = *reinterpret_cast<const uint2*>(base + ob0.z);
            gB[3] = *reinterpret_cast<const uint2*>(base + ob0.w);
            gB[4] = *reinterpret_cast<const uint2*>(base + ob1.x);
            gB[5] = *reinterpret_cast<const uint2*>(base + ob1.y);
            gB[6] = *reinterpret_cast<const uint2*>(base + ob1.z);
            gB[7] = *reinterpret_cast<const uint2*>(base + ob1.w);

            const float wsA[8] = {wa0.x, wa0.y, wa0.z, wa0.w, wa1.x, wa1.y, wa1.z, wa1.w};
            const float wsB[8] = {wb0.x, wb0.y, wb0.z, wb0.w, wb1.x, wb1.y, wb1.z, wb1.w};

            // Vertex A: acc = self + sum_k w_k * g_k, then square.
            {
                const float2 slo = __half22float2(*reinterpret_cast<const __half2*>(&sA.x));
                const float2 shi = __half22float2(*reinterpret_cast<const __half2*>(&sA.y));
                float4 a = make_float4(slo.x, slo.y, shi.x, shi.y);
                #pragma unroll
                for (int k = 0; k < KK; k++) {
                    const float2 lo = __half22float2(*reinterpret_cast<const __half2*>(&gA[k].x));
                    const float2 hi = __half22float2(*reinterpret_cast<const __half2*>(&gA[k].y));
                    a.x = fmaf(wsA[k], lo.x, a.x);
                    a.y = fmaf(wsA[k], lo.y, a.y);
                    a.z = fmaf(wsA[k], hi.x, a.z);
                    a.w = fmaf(wsA[k], hi.y, a.w);
                }
                a.x *= a.x; a.y *= a.y; a.z *= a.z; a.w *= a.w;
                *reinterpret_cast<float4*>(&sn[vlA * SROW + lane * 4]) = a;
            }
            // Vertex B.
            {
                const float2 slo = __half22float2(*reinterpret_cast<const __half2*>(&sB.x));
                const float2 shi = __half22float2(*reinterpret_cast<const __half2*>(&sB.y));
                float4 a = make_float4(slo.x, slo.y, shi.x, shi.y);
                #pragma unroll
                for (int k = 0; k < KK; k++) {
                    const float2 lo = __half22float2(*reinterpret_cast<const __half2*>(&gB[k].x));
                    const float2 hi = __half22float2(*reinterpret_cast<const __half2*>(&gB[k].y));
                    a.x = fmaf(wsB[k], lo.x, a.x);
                    a.y = fmaf(wsB[k], lo.y, a.y);
                    a.z = fmaf(wsB[k], hi.x, a.z);
                    a.w = fmaf(wsB[k], hi.y, a.w);
                }
                a.x *= a.x; a.y *= a.y; a.z *= a.z; a.w *= a.w;
                *reinterpret_cast<float4*>(&sn[vlB * SROW + lane * 4]) = a;
            }
        }
    }
    __syncthreads();

    // Output phase: pure smem -> gmem, fully coalesced over res[b, v0:v0+64, :].
    const size_t base_o = (size_t)v0 * CC;
    #pragma unroll
    for (int it = 0; it < (BB * VPB * CC) / 256; it++) {   // 24 iterations
        const int i  = it * 256 + tid;
        const int b  = i / (VPB * CC);
        const int uu = i - b * (VPB * CC);                  // 0..191
        const int vl = uu / 3;
        const int c  = uu - 3 * vl;
        res[(size_t)b * ROW + base_o + uu] = sn[vl * SROW + b * CC + c];
    }
}

extern "C" void kernel_launch(void* const* d_in, const int* in_sizes, int n_in,
                              void* d_out, int out_size) {
    const float* outp = (const float*)d_in[0];
    const float* tgtp = (const float*)d_in[1];
    const int*   idx  = (const int*)  d_in[2];
    const float* wgt  = (const float*)d_in[3];
    float*       res  = (float*)d_out;

    (void)in_sizes; (void)n_in; (void)out_size;

    diff_transpose_kernel<<<VV / 32, 256>>>(outp, tgtp);
    lap_sq_kernel<<<VV / VPB, 256>>>(idx, wgt, res);
}

// round 12
// speedup vs baseline: 1.0872x; 1.0872x over previous
#include <cuda_runtime.h>
#include <cuda_fp16.h>
#include <cstdint>

// Problem constants (LaplacianReg: B=32, V=65536, K=8, C=3)
#define BB 32
#define VV 65536
#define KK 8
#define CC 3
#define ROW (VV * CC)          // 196608 floats per batch row
#define VB (BB * CC)           // 96 halves per vertex in transposed scratch
#define RB (VB * 2)            // 192 bytes per vertex row (= 12 x 16B chunks)
#define VPB 64                 // vertices per block in kernel 2
#define SROW 100               // smem staging row stride (floats)

// fp16 transposed scratch: d16[v][b*3+c] = out[b][v][c] - tgt[b][v][c].
__device__ __align__(16) __half d16[(size_t)VV * VB];

typedef unsigned long long u64;

// half2 (packed in u32) -> packed f32x2 in one asm block: 2x F2F, pack
// coalesced by the register allocator.
__device__ __forceinline__ u64 h2_to_f32x2(uint32_t h2) {
    u64 r;
    asm("{\n\t"
        ".reg .b16 l, h;\n\t"
        ".reg .f32 fl, fh;\n\t"
        "mov.b32 {l, h}, %1;\n\t"
        "cvt.f32.f16 fl, l;\n\t"
        "cvt.f32.f16 fh, h;\n\t"
        "mov.b64 %0, {fl, fh};\n\t"
        "}" : "=l"(r) : "r"(h2));
    return r;
}

__device__ __forceinline__ u64 ffma2(u64 a, u64 b, u64 c) {
    u64 d;
    asm("fma.rn.f32x2 %0, %1, %2, %3;" : "=l"(d) : "l"(a), "l"(b), "l"(c));
    return d;
}

__device__ __forceinline__ u64 fmul2(u64 a, u64 b) {
    u64 d;
    asm("mul.rn.f32x2 %0, %1, %2;" : "=l"(d) : "l"(a), "l"(b));
    return d;
}

// ---------------------------------------------------------------------------
// Kernel 1: fused difference + transpose (B,V,C) -> fp16 (V, B*C)
// ---------------------------------------------------------------------------
__global__ __launch_bounds__(256) void diff_transpose_kernel(
    const float* __restrict__ outp, const float* __restrict__ tgtp) {
    __shared__ float s[32 * 97];

    const int v0   = blockIdx.x * 32;
    const int warp = threadIdx.x >> 5;
    const int lane = threadIdx.x & 31;

    #pragma unroll
    for (int i = 0; i < 4; i++) {
        const int b = warp + 8 * i;
        const float* po = outp + (size_t)b * ROW + (size_t)v0 * CC;
        const float* pt = tgtp + (size_t)b * ROW + (size_t)v0 * CC;
        #pragma unroll
        for (int r = 0; r < 3; r++) {
            const int u = lane + 32 * r;
            s[b * 97 + u] = po[u] - pt[u];
        }
    }
    __syncthreads();

    #pragma unroll
    for (int i = 0; i < 4; i++) {
        const int vl = warp + 8 * i;
        if (lane < 24) {
            __half h[4];
            #pragma unroll
            for (int j = 0; j < 4; j++) {
                const int u = 4 * lane + j;       // 0..95
                const int b = u / 3;
                const int c = u - 3 * b;
                h[j] = __float2half_rn(s[b * 97 + vl * 3 + c]);
            }
            *reinterpret_cast<uint2*>(d16 + (size_t)(v0 + vl) * VB + 4 * lane) =
                *reinterpret_cast<const uint2*>(h);
        }
    }
}

// ---------------------------------------------------------------------------
// Kernel 2: 9-term gather laplacian + square.
// Paired-vertex LDG.128: lanes 0-11 hold vertex A's 12 16B-chunks, lanes
// 12-23 vertex B's, so ONE LDG.128 gathers neighbor k of both vertices.
// Accumulation uses packed fma.rn.f32x2 (FFMA2); weights pre-duplicated in
// smem as {w,w} so the packed operand is a single LDS.64.
// ---------------------------------------------------------------------------
__global__ __launch_bounds__(256) void lap_sq_kernel(
    const int*   __restrict__ idx,
    const float* __restrict__ wgt,
    float*       __restrict__ res) {
    __shared__ int4   so4[VPB * 2];    // 8 byte-offsets (j*192) per vertex
    __shared__ float2 swd[VPB * KK];   // duplicated weights {w,w}
    __shared__ float  sn[VPB * SROW];  // (lap d)^2, vertex-major

    const int tid = threadIdx.x;
    const int v0  = blockIdx.x * VPB;

    // Stage byte offsets + duplicated weights (coalesced, 512 each).
    #pragma unroll
    for (int t = 0; t < (VPB * KK) / 256; t++) {
        const int i = t * 256 + tid;
        reinterpret_cast<int*>(so4)[i] = idx[(size_t)v0 * KK + i] * RB;
        const float w = wgt[(size_t)v0 * KK + i];
        swd[i] = make_float2(w, w);
    }
    __syncthreads();

    const int warp    = tid >> 5;
    const int lane    = tid & 31;
    const int h       = (lane >= 12) ? 1 : 0;   // vertex-within-pair
    const int c       = lane - h * 12;          // chunk 0..11
    const bool active = lane < 24;
    const char* gbase = reinterpret_cast<const char*>(d16) + c * 16;

    #pragma unroll
    for (int vp = 0; vp < 4; vp++) {
        const int vl = warp * 8 + 2 * vp + h;   // this lane's vertex

        // Per-lane neighbor byte-offsets (2 distinct LDS addrs per warp).
        const int4 o0 = so4[vl * 2];
        const int4 o1 = so4[vl * 2 + 1];
        const u64* wp = reinterpret_cast<const u64*>(&swd[vl * KK]);

        if (active) {
            // Batch 1: self + neighbors 0..3 (5 LDG.128 in flight).
            const uint4 gs = *reinterpret_cast<const uint4*>(gbase + (v0 + vl) * RB);
            const uint4 g0 = *reinterpret_cast<const uint4*>(gbase + o0.x);
            const uint4 g1 = *reinterpret_cast<const uint4*>(gbase + o0.y);
            const uint4 g2 = *reinterpret_cast<const uint4*>(gbase + o0.z);
            const uint4 g3 = *reinterpret_cast<const uint4*>(gbase + o0.w);

            u64 a0 = h2_to_f32x2(gs.x);
            u64 a1 = h2_to_f32x2(gs.y);
            u64 a2 = h2_to_f32x2(gs.z);
            u64 a3 = h2_to_f32x2(gs.w);

            {
                const u64 w0 = wp[0];
                a0 = ffma2(h2_to_f32x2(g0.x), w0, a0);
                a1 = ffma2(h2_to_f32x2(g0.y), w0, a1);
                a2 = ffma2(h2_to_f32x2(g0.z), w0, a2);
                a3 = ffma2(h2_to_f32x2(g0.w), w0, a3);
                const u64 w1 = wp[1];
                a0 = ffma2(h2_to_f32x2(g1.x), w1, a0);
                a1 = ffma2(h2_to_f32x2(g1.y), w1, a1);
                a2 = ffma2(h2_to_f32x2(g1.z), w1, a2);
                a3 = ffma2(h2_to_f32x2(g1.w), w1, a3);
                const u64 w2 = wp[2];
                a0 = ffma2(h2_to_f32x2(g2.x), w2, a0);
                a1 = ffma2(h2_to_f32x2(g2.y), w2, a1);
                a2 = ffma2(h2_to_f32x2(g2.z), w2, a2);
                a3 = ffma2(h2_to_f32x2(g2.w), w2, a3);
                const u64 w3 = wp[3];
                a0 = ffma2(h2_to_f32x2(g3.x), w3, a0);
                a1 = ffma2(h2_to_f32x2(g3.y), w3, a1);
                a2 = ffma2(h2_to_f32x2(g3.z), w3, a2);
                a3 = ffma2(h2_to_f32x2(g3.w), w3, a3);
            }

            // Batch 2: neighbors 4..7.
            const uint4 g4 = *reinterpret_cast<const uint4*>(gbase + o1.x);
            const uint4 g5 = *reinterpret_cast<const uint4*>(gbase + o1.y);
            const uint4 g6 = *reinterpret_cast<const uint4*>(gbase + o1.z);
            const uint4 g7 = *reinterpret_cast<const uint4*>(gbase + o1.w);
            {
                const u64 w4 = wp[4];
                a0 = ffma2(h2_to_f32x2(g4.x), w4, a0);
                a1 = ffma2(h2_to_f32x2(g4.y), w4, a1);
                a2 = ffma2(h2_to_f32x2(g4.z), w4, a2);
                a3 = ffma2(h2_to_f32x2(g4.w), w4, a3);
                const u64 w5 = wp[5];
                a0 = ffma2(h2_to_f32x2(g5.x), w5, a0);
                a1 = ffma2(h2_to_f32x2(g5.y), w5, a1);
                a2 = ffma2(h2_to_f32x2(g5.z), w5, a2);
                a3 = ffma2(h2_to_f32x2(g5.w), w5, a3);
                const u64 w6 = wp[6];
                a0 = ffma2(h2_to_f32x2(g6.x), w6, a0);
                a1 = ffma2(h2_to_f32x2(g6.y), w6, a1);
                a2 = ffma2(h2_to_f32x2(g6.z), w6, a2);
                a3 = ffma2(h2_to_f32x2(g6.w), w6, a3);
                const u64 w7 = wp[7];
                a0 = ffma2(h2_to_f32x2(g7.x), w7, a0);
                a1 = ffma2(h2_to_f32x2(g7.y), w7, a1);
                a2 = ffma2(h2_to_f32x2(g7.z), w7, a2);
                a3 = ffma2(h2_to_f32x2(g7.w), w7, a3);
            }

            // Square (packed) and stage: lane covers floats [c*8, c*8+8).
            a0 = fmul2(a0, a0);
            a1 = fmul2(a1, a1);
            a2 = fmul2(a2, a2);
            a3 = fmul2(a3, a3);
            u64* dst = reinterpret_cast<u64*>(&sn[vl * SROW + c * 8]);
            dst[0] = a0; dst[1] = a1; dst[2] = a2; dst[3] = a3;
        }
    }
    __syncthreads();

    // Output phase: pure smem -> gmem, fully coalesced over res[b, v0:v0+64, :].
    const size_t base_o = (size_t)v0 * CC;
    #pragma unroll
    for (int it = 0; it < (BB * VPB * CC) / 256; it++) {   // 24 iterations
        const int i  = it * 256 + tid;
        const int b  = i / (VPB * CC);
        const int uu = i - b * (VPB * CC);                  // 0..191
        const int vl = uu / 3;
        const int cc = uu - 3 * vl;
        res[(size_t)b * ROW + base_o + uu] = sn[vl * SROW + b * CC + cc];
    }
}

extern "C" void kernel_launch(void* const* d_in, const int* in_sizes, int n_in,
                              void* d_out, int out_size) {
    const float* outp = (const float*)d_in[0];
    const float* tgtp = (const float*)d_in[1];
    const int*   idx  = (const int*)  d_in[2];
    const float* wgt  = (const float*)d_in[3];
    float*       res  = (float*)d_out;

    (void)in_sizes; (void)n_in; (void)out_size;

    diff_transpose_kernel<<<VV / 32, 256>>>(outp, tgtp);
    lap_sq_kernel<<<VV / VPB, 256>>>(idx, wgt, res);
}